// round 16
// baseline (speedup 1.0000x reference)
#include <cuda_runtime.h>
#include <cuda_bf16.h>
#include <cstdint>

#define BB 16
#define SS 2048
#define DD 512
#define CC 8192
#define MM (BB*SS)

#define SPLITS 4
#define CPS (CC/SPLITS)          // 2048 codes per split
#define NTILE 256                // codes per tile
#define NTILES (CPS/NTILE)       // 8 tiles per split
#define TOTCH (NTILES*4)         // 32 K-chunks (128 bytes) per CTA
#define CAND 32
#define TAU 0.125f
#define RMINIT 1.5f

// ---------------- scratch ----------------------------------------------------
__device__ __align__(128) float   g_half_e2[CC];
__device__ __align__(128) float   g_se[CC];
__device__ __align__(128) float   g_sx[MM];
__device__ __align__(128) int8_t  g_e8[(size_t)CC * DD];   // 4 MB
__device__ __align__(128) int8_t  g_x8[(size_t)MM * DD];   // 16 MB
__device__ __align__(128) int     g_cand[(size_t)MM * SPLITS * CAND];
__device__ __align__(128) int     g_cnt[(size_t)MM * SPLITS];

// ---------------- helpers ----------------------------------------------------
__device__ __forceinline__ uint32_t smem_u32(const void* p) {
    uint32_t a;
    asm("{ .reg .u64 t; cvta.to.shared.u64 t, %1; cvt.u32.u64 %0, t; }"
        : "=r"(a) : "l"(p));
    return a;
}

#define CP_ASYNC16(dst, src) \
    asm volatile("cp.async.cg.shared.global [%0], [%1], 16;" \
                 :: "r"(dst), "l"(__cvta_generic_to_global(src)) : "memory")
#define CP_COMMIT  asm volatile("cp.async.commit_group;" ::: "memory")
#define CP_WAIT(n) asm volatile("cp.async.wait_group %0;" :: "n"(n) : "memory")

#define LDSM4(r, addr) \
    asm volatile("ldmatrix.sync.aligned.m8n8.x4.shared.b16 {%0,%1,%2,%3}, [%4];" \
                 : "=r"((r)[0]), "=r"((r)[1]), "=r"((r)[2]), "=r"((r)[3]) : "r"(addr))

#define IMMA16832(d, a, b0, b1) \
    asm volatile("mma.sync.aligned.m16n8k32.row.col.s32.s8.s8.s32 " \
                 "{%0,%1,%2,%3}, {%4,%5,%6,%7}, {%8,%9}, {%0,%1,%2,%3};" \
                 : "+r"((d)[0]), "+r"((d)[1]), "+r"((d)[2]), "+r"((d)[3]) \
                 : "r"((a)[0]), "r"((a)[1]), "r"((a)[2]), "r"((a)[3]), \
                   "r"(b0), "r"(b1))

__device__ __forceinline__ int8_t q8(float v, float inv_s) {
    int q = __float2int_rn(v * inv_s);
    q = max(-127, min(127, q));
    return (int8_t)q;
}

// ---------------- prep kernels ------------------------------------------------
// warp per code: amax -> se, quantize, 0.5*||e||^2 (exact fp32). Zero g_cnt.
__global__ void prep_embed(const float* __restrict__ embed) {
    int c = blockIdx.x * 8 + (threadIdx.x >> 5);
    int lane = threadIdx.x & 31;
    const float4* e4 = (const float4*)embed;
    float4 v[4];
    float s = 0.f, am = 0.f;
#pragma unroll
    for (int j = 0; j < 4; j++) {
        v[j] = e4[(size_t)c * (DD / 4) + j * 32 + lane];
        s += v[j].x * v[j].x + v[j].y * v[j].y + v[j].z * v[j].z + v[j].w * v[j].w;
        am = fmaxf(am, fmaxf(fmaxf(fabsf(v[j].x), fabsf(v[j].y)),
                             fmaxf(fabsf(v[j].z), fabsf(v[j].w))));
    }
#pragma unroll
    for (int off = 16; off; off >>= 1) {
        s  += __shfl_xor_sync(0xffffffffu, s, off);
        am  = fmaxf(am, __shfl_xor_sync(0xffffffffu, am, off));
    }
    float se = (am > 0.f) ? am / 127.f : 1.f;
    float inv = 1.f / se;
    if (lane == 0) { g_half_e2[c] = 0.5f * s; g_se[c] = se; }
    // each lane quantizes its own 16 contiguous elems? v[j] are strided (j*32+lane).
    // store back at the same strided positions (4 bytes per float4 -> uchar4).
    uchar4* e8v = (uchar4*)g_e8;
#pragma unroll
    for (int j = 0; j < 4; j++) {
        uchar4 o;
        o.x = (unsigned char)q8(v[j].x, inv);
        o.y = (unsigned char)q8(v[j].y, inv);
        o.z = (unsigned char)q8(v[j].z, inv);
        o.w = (unsigned char)q8(v[j].w, inv);
        e8v[(size_t)c * (DD / 4) + j * 32 + lane] = o;
    }
    int gid = blockIdx.x * 256 + threadIdx.x;
    if (gid < MM * SPLITS) g_cnt[gid] = 0;
}

// warp per token: amax -> sx, quantize.
__global__ void prep_x(const float* __restrict__ x) {
    int t = blockIdx.x * 8 + (threadIdx.x >> 5);
    int lane = threadIdx.x & 31;
    const float4* x4 = (const float4*)x;
    float4 v[4];
    float am = 0.f;
#pragma unroll
    for (int j = 0; j < 4; j++) {
        v[j] = x4[(size_t)t * (DD / 4) + j * 32 + lane];
        am = fmaxf(am, fmaxf(fmaxf(fabsf(v[j].x), fabsf(v[j].y)),
                             fmaxf(fabsf(v[j].z), fabsf(v[j].w))));
    }
#pragma unroll
    for (int off = 16; off; off >>= 1)
        am = fmaxf(am, __shfl_xor_sync(0xffffffffu, am, off));
    float sx = (am > 0.f) ? am / 127.f : 1.f;
    float inv = 1.f / sx;
    if (lane == 0) g_sx[t] = sx;
    uchar4* x8v = (uchar4*)g_x8;
#pragma unroll
    for (int j = 0; j < 4; j++) {
        uchar4 o;
        o.x = (unsigned char)q8(v[j].x, inv);
        o.y = (unsigned char)q8(v[j].y, inv);
        o.z = (unsigned char)q8(v[j].z, inv);
        o.w = (unsigned char)q8(v[j].w, inv);
        x8v[(size_t)t * (DD / 4) + j * 32 + lane] = o;
    }
}

// ---------------- IMMA candidate pass -----------------------------------------
// grid (256, 4). CTA: 128 tokens x 2048-code split. 16 warps, warp tile 32x64.
// A: 128 rows x 512B int8 resident (64KB). B: 256 codes x 128B chunks, 3-stage.
#define SMEM_A   65536
#define SMEM_BCH 32768
#define SMEM_DYN (SMEM_A + 3 * SMEM_BCH)

__global__ __launch_bounds__(512, 1)
void vq_gemm(const int* __restrict__ ilen) {
    extern __shared__ char dsm[];
    __shared__ float sSE[NTILE];
    __shared__ float sHE[NTILE];
    __shared__ float sSX[128];

    const int tid = threadIdx.x, lane = tid & 31, wid = tid >> 5;
    const int m0 = blockIdx.x * 128;
    if ((m0 & (SS - 1)) >= ilen[m0 >> 11]) return;
    const int split = blockIdx.y;
    const int split0 = split * CPS;

    const uint32_t sA = smem_u32(dsm);
    const uint32_t sB = sA + SMEM_A;

    {   // A prefetch: 128 rows x 512B, swizzle low-3 bits of 16B-group index
        const int8_t* xb = g_x8 + (size_t)m0 * DD;
        for (int i = tid; i < 4096; i += 512) {
            int row = i >> 5, g = i & 31;
            uint32_t dst = sA + row * 512 + ((g ^ (row & 7)) << 4);
            CP_ASYNC16(dst, xb + (size_t)row * DD + g * 16);
        }
    }
    auto prefB = [&](int gi) {   // 256 codes x 128B
        const int8_t* src0 =
            g_e8 + (size_t)(split0 + (gi >> 2) * NTILE) * DD + (gi & 3) * 128;
        uint32_t bb = sB + (gi % 3) * SMEM_BCH;
        for (int i = tid; i < 2048; i += 512) {
            int row = i >> 3, g = i & 7;
            uint32_t dst = bb + row * 128 + ((g ^ (row & 7)) << 4);
            CP_ASYNC16(dst, src0 + (size_t)row * DD + g * 16);
        }
    };
    prefB(0); CP_COMMIT;
    prefB(1); CP_COMMIT;

    if (tid < 128) sSX[tid] = g_sx[m0 + tid];

    const int wm = wid >> 2, wn = wid & 3;
    // ldsm lane roles
    const int lrow16 = lane & 15;          // row within 16-row block
    const int lhalf  = lane >> 4;          // 0: bytes 0-15, 1: bytes 16-31

    int acc[2][8][4];
    float runmax[2][2] = {{RMINIT, RMINIT}, {RMINIT, RMINIT}};

    for (int gi = 0; gi < TOTCH; gi++) {
        const int nt = gi >> 2, kb = gi & 3;
        if (gi < TOTCH - 1) CP_WAIT(1); else CP_WAIT(0);
        __syncthreads();
        if (gi + 2 < TOTCH) { prefB(gi + 2); CP_COMMIT; }

        if (kb == 0) {
            if (tid < NTILE) {
                sSE[tid] = g_se[split0 + nt * NTILE + tid];
                sHE[tid] = g_half_e2[split0 + nt * NTILE + tid];
            }
#pragma unroll
            for (int mt = 0; mt < 2; mt++)
#pragma unroll
                for (int j = 0; j < 8; j++)
#pragma unroll
                    for (int q = 0; q < 4; q++) acc[mt][j][q] = 0;
        }

        const uint32_t bb = sB + (gi % 3) * SMEM_BCH;
#pragma unroll
        for (int ks = 0; ks < 4; ks++) {            // K=32 per step
            uint32_t a[2][4];
#pragma unroll
            for (int mt = 0; mt < 2; mt++) {
                int row = wm * 32 + mt * 16 + lrow16;
                int g = kb * 8 + ks * 2 + lhalf;    // 16B group within 512B row
                LDSM4(a[mt], sA + row * 512 + ((g ^ (row & 7)) << 4));
            }
#pragma unroll
            for (int p = 0; p < 4; p++) {           // 16 codes per ldsm.x4
                uint32_t b[4];
                int code = wn * 64 + p * 16 + lrow16;
                int g = ks * 2 + lhalf;             // within 128B row
                LDSM4(b, bb + code * 128 + ((g ^ (code & 7)) << 4));
#pragma unroll
                for (int mt = 0; mt < 2; mt++) {
                    IMMA16832(acc[mt][p * 2],     a[mt], b[0], b[2]);
                    IMMA16832(acc[mt][p * 2 + 1], a[mt], b[1], b[3]);
                }
            }
        }

        if (kb == 3) {   // epilogue for this 256-code tile
            const int c0 = split0 + nt * NTILE;
            const int colb = wn * 64 + (lane & 3) * 2;
#pragma unroll
            for (int mt = 0; mt < 2; mt++)
#pragma unroll
                for (int hh = 0; hh < 2; hh++) {
                    const float sxv = sSX[wm * 32 + mt * 16 + hh * 8 + (lane >> 2)];
                    float m = runmax[mt][hh];
#pragma unroll
                    for (int n8 = 0; n8 < 8; n8++)
#pragma unroll
                        for (int par = 0; par < 2; par++) {
                            int col = colb + n8 * 8 + par;
                            float v = fmaf((float)acc[mt][n8][hh * 2 + par],
                                           sxv * sSE[col], -sHE[col]);
                            m = fmaxf(m, v);
                        }
                    m = fmaxf(m, __shfl_xor_sync(0xffffffffu, m, 1));
                    m = fmaxf(m, __shfl_xor_sync(0xffffffffu, m, 2));
                    runmax[mt][hh] = m;
                    const float thr = m - TAU;
                    const int row = m0 + wm * 32 + mt * 16 + hh * 8 + (lane >> 2);
#pragma unroll
                    for (int n8 = 0; n8 < 8; n8++)
#pragma unroll
                        for (int par = 0; par < 2; par++) {
                            int col = colb + n8 * 8 + par;
                            float v = fmaf((float)acc[mt][n8][hh * 2 + par],
                                           sxv * sSE[col], -sHE[col]);
                            if (v >= thr) {
                                int pos = atomicAdd(&g_cnt[(size_t)row * SPLITS + split], 1);
                                if (pos < CAND)
                                    g_cand[((size_t)row * SPLITS + split) * CAND + pos] =
                                        c0 + col;
                            }
                        }
                }
        }
    }
}

// ---------------- exact fp32 rescore + gather ----------------------------------
__global__ __launch_bounds__(256)
void vq_rescore(const float* __restrict__ x, const int* __restrict__ ilen,
                const float* __restrict__ embed,
                float* __restrict__ outq, float* __restrict__ outi) {
    const int wid = threadIdx.x >> 5, lane = threadIdx.x & 31;
    const int t = blockIdx.x * 8 + wid;
    const int s = t & (SS - 1);
    const int len = ilen[t >> 11];
    float4* oq = (float4*)outq;

    if (s >= len) {
        float4 z = make_float4(0.f, 0.f, 0.f, 0.f);
#pragma unroll
        for (int j = 0; j < 4; j++) oq[(size_t)t * (DD / 4) + j * 32 + lane] = z;
        if (outi && lane == 0) outi[t] = -1.0f;
        return;
    }

    const float4* x4 = (const float4*)x;
    const float4* e4 = (const float4*)embed;
    float4 xr[4];
#pragma unroll
    for (int j = 0; j < 4; j++) xr[j] = x4[(size_t)t * (DD / 4) + j * 32 + lane];

    float best = -3.402823466e38f;
    int bi = 0;
#pragma unroll 1
    for (int sp = 0; sp < SPLITS; sp++) {
        int cn = g_cnt[(size_t)t * SPLITS + sp];
        if (cn > CAND) cn = CAND;
        const int* cl = &g_cand[((size_t)t * SPLITS + sp) * CAND];
        int k = 0;
#pragma unroll 1
        for (; k + 1 < cn; k += 2) {
            int i0 = cl[k], i1 = cl[k + 1];
            float a0 = 0.f, a1 = 0.f;
#pragma unroll
            for (int j = 0; j < 4; j++) {
                float4 e0 = e4[(size_t)i0 * (DD / 4) + j * 32 + lane];
                float4 e1 = e4[(size_t)i1 * (DD / 4) + j * 32 + lane];
                a0 += xr[j].x * e0.x + xr[j].y * e0.y + xr[j].z * e0.z + xr[j].w * e0.w;
                a1 += xr[j].x * e1.x + xr[j].y * e1.y + xr[j].z * e1.z + xr[j].w * e1.w;
            }
#pragma unroll
            for (int off = 16; off; off >>= 1) {
                a0 += __shfl_xor_sync(0xffffffffu, a0, off);
                a1 += __shfl_xor_sync(0xffffffffu, a1, off);
            }
            float s0 = a0 - g_half_e2[i0];
            float s1 = a1 - g_half_e2[i1];
            if (s0 > best || (s0 == best && i0 < bi)) { best = s0; bi = i0; }
            if (s1 > best || (s1 == best && i1 < bi)) { best = s1; bi = i1; }
        }
        if (k < cn) {
            int i0 = cl[k];
            float a0 = 0.f;
#pragma unroll
            for (int j = 0; j < 4; j++) {
                float4 e0 = e4[(size_t)i0 * (DD / 4) + j * 32 + lane];
                a0 += xr[j].x * e0.x + xr[j].y * e0.y + xr[j].z * e0.z + xr[j].w * e0.w;
            }
#pragma unroll
            for (int off = 16; off; off >>= 1) a0 += __shfl_xor_sync(0xffffffffu, a0, off);
            float s0 = a0 - g_half_e2[i0];
            if (s0 > best || (s0 == best && i0 < bi)) { best = s0; bi = i0; }
        }
    }
#pragma unroll
    for (int j = 0; j < 4; j++)
        oq[(size_t)t * (DD / 4) + j * 32 + lane] = e4[(size_t)bi * (DD / 4) + j * 32 + lane];
    if (outi && lane == 0) outi[t] = (float)bi;
}

// ---------------- launch --------------------------------------------------------
extern "C" void kernel_launch(void* const* d_in, const int* in_sizes, int n_in,
                              void* d_out, int out_size) {
    const float* xp = nullptr;
    const int* lp = nullptr;
    const float* ep = nullptr;
    for (int i = 0; i < n_in; i++) {
        if (in_sizes[i] == MM * DD)      xp = (const float*)d_in[i];
        else if (in_sizes[i] == CC * DD) ep = (const float*)d_in[i];
        else if (in_sizes[i] == BB)      lp = (const int*)d_in[i];
    }
    float* oq = (float*)d_out;
    float* oi = (out_size >= (int)((size_t)MM * DD + MM)) ? oq + (size_t)MM * DD : nullptr;

    cudaFuncSetAttribute(vq_gemm, cudaFuncAttributeMaxDynamicSharedMemorySize, SMEM_DYN);

    prep_embed<<<CC / 8, 256>>>(ep);
    prep_x<<<MM / 8, 256>>>(xp);
    vq_gemm<<<dim3(256, SPLITS), 512, SMEM_DYN>>>(lp);
    vq_rescore<<<MM / 8, 256>>>(xp, lp, ep, oq, oi);
}

// round 17
// speedup vs baseline: 1.8575x; 1.8575x over previous
#include <cuda_runtime.h>
#include <cuda_bf16.h>
#include <cstdint>

#define BB 16
#define SS 2048
#define DD 512
#define CC 8192
#define MM (BB*SS)

#define SPLITS 8
#define CPS (CC/SPLITS)          // 1024 codes per split
#define NTILE 256                // codes per tile (B chunk width)
#define NTILES (CPS/NTILE)       // 4 tiles per split
#define TOTCH (NTILES*8)         // 32 K-chunks per CTA
#define CAND 32
#define TAU 0.09375f
#define RMINIT 1.5f

// ---------------- scratch (16B-aligned for cp.async) -------------------------
__device__ __align__(128) float          g_half_e2[CC];
__device__ __align__(128) __nv_bfloat16  g_ebf[(size_t)CC * DD];   // 8 MB
__device__ __align__(128) __nv_bfloat16  g_xbf[(size_t)MM * DD];   // 32 MB
__device__ __align__(128) int            g_cand[(size_t)MM * SPLITS * CAND];
__device__ __align__(128) int            g_cnt[(size_t)MM * SPLITS];
__device__ __align__(128) unsigned long long g_best[MM];

// ---------------- helpers ----------------------------------------------------
__device__ __forceinline__ uint32_t smem_u32(const void* p) {
    uint32_t a;
    asm("{ .reg .u64 t; cvta.to.shared.u64 t, %1; cvt.u32.u64 %0, t; }"
        : "=r"(a) : "l"(p));
    return a;
}
__device__ __forceinline__ uint32_t ford(float f) {   // order-preserving float->u32
    uint32_t u = __float_as_uint(f);
    return (u & 0x80000000u) ? ~u : (u | 0x80000000u);
}

#define CP_ASYNC16(dst, src) \
    asm volatile("cp.async.cg.shared.global [%0], [%1], 16;" \
                 :: "r"(dst), "l"(__cvta_generic_to_global(src)) : "memory")
#define CP_COMMIT  asm volatile("cp.async.commit_group;" ::: "memory")
#define CP_WAIT(n) asm volatile("cp.async.wait_group %0;" :: "n"(n) : "memory")

#define LDSM4(r, addr) \
    asm volatile("ldmatrix.sync.aligned.m8n8.x4.shared.b16 {%0,%1,%2,%3}, [%4];" \
                 : "=r"((r)[0]), "=r"((r)[1]), "=r"((r)[2]), "=r"((r)[3]) : "r"(addr))

#define MMA16816(d, a, b0, b1) \
    asm volatile("mma.sync.aligned.m16n8k16.row.col.f32.bf16.bf16.f32 " \
                 "{%0,%1,%2,%3}, {%4,%5,%6,%7}, {%8,%9}, {%0,%1,%2,%3};" \
                 : "+f"((d)[0]), "+f"((d)[1]), "+f"((d)[2]), "+f"((d)[3]) \
                 : "r"((a)[0]), "r"((a)[1]), "r"((a)[2]), "r"((a)[3]), \
                   "r"(b0), "r"(b1))

// ---------------- prep kernels ------------------------------------------------
__global__ void prep_embed(const float* __restrict__ embed) {
    int c = blockIdx.x * 8 + (threadIdx.x >> 5);
    int lane = threadIdx.x & 31;
    const float4* e4 = (const float4*)embed;
    uint2* eb = (uint2*)g_ebf;
    float s = 0.f;
#pragma unroll
    for (int j = 0; j < 4; j++) {
        float4 v = e4[(size_t)c * (DD / 4) + j * 32 + lane];
        s += v.x * v.x + v.y * v.y + v.z * v.z + v.w * v.w;
        __nv_bfloat162 p0 = __floats2bfloat162_rn(v.x, v.y);
        __nv_bfloat162 p1 = __floats2bfloat162_rn(v.z, v.w);
        uint2 u;
        u.x = *reinterpret_cast<uint32_t*>(&p0);
        u.y = *reinterpret_cast<uint32_t*>(&p1);
        eb[(size_t)c * (DD / 4) + j * 32 + lane] = u;
    }
#pragma unroll
    for (int off = 16; off; off >>= 1) s += __shfl_xor_sync(0xffffffffu, s, off);
    if (lane == 0) g_half_e2[c] = 0.5f * s;
}

__global__ void prep_x(const float* __restrict__ x) {
    int t = blockIdx.x * 8 + (threadIdx.x >> 5);
    int lane = threadIdx.x & 31;
    const float4* x4 = (const float4*)x;
    uint2* xb = (uint2*)g_xbf;
#pragma unroll
    for (int j = 0; j < 4; j++) {
        float4 v = x4[(size_t)t * (DD / 4) + j * 32 + lane];
        __nv_bfloat162 p0 = __floats2bfloat162_rn(v.x, v.y);
        __nv_bfloat162 p1 = __floats2bfloat162_rn(v.z, v.w);
        uint2 u;
        u.x = *reinterpret_cast<uint32_t*>(&p0);
        u.y = *reinterpret_cast<uint32_t*>(&p1);
        xb[(size_t)t * (DD / 4) + j * 32 + lane] = u;
    }
    if (lane == 0) g_best[t] = 0ull;
    // zero candidate counters (MM*SPLITS = 8 per token here)
    int base = t * SPLITS;
    if (lane < SPLITS) g_cnt[base + lane] = 0;
}

// ---------------- HMMA candidate pass -----------------------------------------
// grid (256, 8). CTA: 128 tokens x 1024-code split. 16 warps, warp tile 32x64.
#define SMEM_A   131072
#define SMEM_BCH 32768
#define SMEM_DYN (SMEM_A + 3 * SMEM_BCH)

__global__ __launch_bounds__(512, 1)
void vq_gemm(const int* __restrict__ ilen) {
    extern __shared__ char dsm[];
    __shared__ float sHE[NTILE];

    const int tid = threadIdx.x, lane = tid & 31, wid = tid >> 5;
    const int m0 = blockIdx.x * 128;
    if ((m0 & (SS - 1)) >= ilen[m0 >> 11]) return;   // fully masked tile
    const int split = blockIdx.y;
    const int split0 = split * CPS;

    const uint32_t sA = smem_u32(dsm);
    const uint32_t sB = sA + SMEM_A;

    {   // A prefetch: 128 tokens x 512 k, swizzled rows of 1KB
        const __nv_bfloat16* xb = g_xbf + (size_t)m0 * DD;
        for (int i = tid; i < 8192; i += 512) {
            int row = i >> 6, g = i & 63;
            uint32_t dst = sA + row * 1024 + ((g ^ (row & 7)) << 4);
            CP_ASYNC16(dst, xb + (size_t)row * DD + g * 8);
        }
    }
    auto prefB = [&](int gi) {   // 256 codes x 64 k = 32 KB
        const __nv_bfloat16* src0 =
            g_ebf + (size_t)(split0 + (gi >> 3) * NTILE) * DD + (gi & 7) * 64;
        uint32_t bb = sB + (gi % 3) * SMEM_BCH;
        for (int i = tid; i < 2048; i += 512) {
            int row = i >> 3, g = i & 7;
            uint32_t dst = bb + row * 128 + ((g ^ (row & 7)) << 4);
            CP_ASYNC16(dst, src0 + (size_t)row * DD + g * 8);
        }
    };
    prefB(0); CP_COMMIT;
    prefB(1); CP_COMMIT;

    const int wm = wid >> 2, wn = wid & 3;                 // 4 x 4 warp grid
    const int rA0 = wm * 32 + (lane & 15);
    const int kgA_off = lane >> 4;
    const int rB0 = wn * 64 + (lane & 7) + ((lane >> 4) << 3);
    const int kgB_off = (lane >> 3) & 1;

    float acc[2][8][4];
    float runmax[2][2] = {{RMINIT, RMINIT}, {RMINIT, RMINIT}};

    for (int gi = 0; gi < TOTCH; gi++) {
        const int nt = gi >> 3, ck = gi & 7;
        if (gi < TOTCH - 1) CP_WAIT(1); else CP_WAIT(0);
        __syncthreads();
        if (gi + 2 < TOTCH) { prefB(gi + 2); CP_COMMIT; }

        if (ck == 0) {
            if (tid < NTILE) sHE[tid] = g_half_e2[split0 + nt * NTILE + tid];
#pragma unroll
            for (int mt = 0; mt < 2; mt++)
#pragma unroll
                for (int j = 0; j < 8; j++)
#pragma unroll
                    for (int q = 0; q < 4; q++) acc[mt][j][q] = 0.f;
        }

        const uint32_t bb = sB + (gi % 3) * SMEM_BCH;

        uint32_t bfr[2][4][4];
        {   // prime B frags for ks=0
            const int kgB = kgB_off;
#pragma unroll
            for (int np = 0; np < 4; np++) {
                int row = rB0 + np * 16;
                LDSM4(bfr[0][np], bb + row * 128 + ((kgB ^ (row & 7)) << 4));
            }
        }
#pragma unroll
        for (int ks = 0; ks < 4; ks++) {
            const int cur = ks & 1;
            if (ks < 3) {
                const int kgB = (ks + 1) * 2 + kgB_off;
#pragma unroll
                for (int np = 0; np < 4; np++) {
                    int row = rB0 + np * 16;
                    LDSM4(bfr[cur ^ 1][np], bb + row * 128 + ((kgB ^ (row & 7)) << 4));
                }
            }
            uint32_t a[2][4];
            const int kgA = ck * 8 + ks * 2 + kgA_off;
#pragma unroll
            for (int mt = 0; mt < 2; mt++) {
                int row = rA0 + mt * 16;
                LDSM4(a[mt], sA + row * 1024 + ((kgA ^ (row & 7)) << 4));
            }
#pragma unroll
            for (int mt = 0; mt < 2; mt++)
#pragma unroll
                for (int np = 0; np < 4; np++) {
                    MMA16816(acc[mt][np * 2],     a[mt], bfr[cur][np][0], bfr[cur][np][1]);
                    MMA16816(acc[mt][np * 2 + 1], a[mt], bfr[cur][np][2], bfr[cur][np][3]);
                }
        }

        if (ck == 7) {   // epilogue for this 256-code tile
            const int c0 = split0 + nt * NTILE;
            const int colb = wn * 64 + (lane & 3) * 2;
#pragma unroll
            for (int mt = 0; mt < 2; mt++)
#pragma unroll
                for (int hh = 0; hh < 2; hh++) {
                    float m = runmax[mt][hh];
#pragma unroll
                    for (int n8 = 0; n8 < 8; n8++) {
                        m = fmaxf(m, acc[mt][n8][hh * 2]     - sHE[colb + n8 * 8]);
                        m = fmaxf(m, acc[mt][n8][hh * 2 + 1] - sHE[colb + n8 * 8 + 1]);
                    }
                    m = fmaxf(m, __shfl_xor_sync(0xffffffffu, m, 1));
                    m = fmaxf(m, __shfl_xor_sync(0xffffffffu, m, 2));
                    runmax[mt][hh] = m;
                    const float thr = m - TAU;
                    const int row = m0 + wm * 32 + mt * 16 + hh * 8 + (lane >> 2);
#pragma unroll
                    for (int n8 = 0; n8 < 8; n8++)
#pragma unroll
                        for (int par = 0; par < 2; par++) {
                            float v = acc[mt][n8][hh * 2 + par] - sHE[colb + n8 * 8 + par];
                            if (v >= thr) {
                                int pos = atomicAdd(&g_cnt[(size_t)row * SPLITS + split], 1);
                                if (pos < CAND)
                                    g_cand[((size_t)row * SPLITS + split) * CAND + pos] =
                                        c0 + colb + n8 * 8 + par;
                            }
                        }
                }
        }
    }
}

// ---------------- exact fp32 rescore: warp per (token, split) -----------------
__global__ __launch_bounds__(256)
void vq_score(const float* __restrict__ x, const int* __restrict__ ilen,
              const float* __restrict__ embed) {
    const int wid = threadIdx.x >> 5, lane = threadIdx.x & 31;
    const int t = blockIdx.x * 8 + wid;
    const int sp = blockIdx.y;
    if ((t & (SS - 1)) >= ilen[t >> 11]) return;          // masked token

    int cn = g_cnt[(size_t)t * SPLITS + sp];
    if (cn == 0) return;
    if (cn > CAND) cn = CAND;
    const int* cl = &g_cand[((size_t)t * SPLITS + sp) * CAND];

    const float4* x4 = (const float4*)x;
    const float4* e4 = (const float4*)embed;
    float4 xr[4];
#pragma unroll
    for (int j = 0; j < 4; j++) xr[j] = x4[(size_t)t * (DD / 4) + j * 32 + lane];

    float best = -3.402823466e38f;
    int bi = 0;
    int k = 0;
#pragma unroll 1
    for (; k + 1 < cn; k += 2) {
        int i0 = cl[k], i1 = cl[k + 1];
        float a0 = 0.f, a1 = 0.f;
#pragma unroll
        for (int j = 0; j < 4; j++) {
            float4 e0 = e4[(size_t)i0 * (DD / 4) + j * 32 + lane];
            float4 e1 = e4[(size_t)i1 * (DD / 4) + j * 32 + lane];
            a0 += xr[j].x * e0.x + xr[j].y * e0.y + xr[j].z * e0.z + xr[j].w * e0.w;
            a1 += xr[j].x * e1.x + xr[j].y * e1.y + xr[j].z * e1.z + xr[j].w * e1.w;
        }
#pragma unroll
        for (int off = 16; off; off >>= 1) {
            a0 += __shfl_xor_sync(0xffffffffu, a0, off);
            a1 += __shfl_xor_sync(0xffffffffu, a1, off);
        }
        float s0 = a0 - g_half_e2[i0];
        float s1 = a1 - g_half_e2[i1];
        if (s0 > best || (s0 == best && i0 < bi)) { best = s0; bi = i0; }
        if (s1 > best || (s1 == best && i1 < bi)) { best = s1; bi = i1; }
    }
    if (k < cn) {
        int i0 = cl[k];
        float a0 = 0.f;
#pragma unroll
        for (int j = 0; j < 4; j++) {
            float4 e0 = e4[(size_t)i0 * (DD / 4) + j * 32 + lane];
            a0 += xr[j].x * e0.x + xr[j].y * e0.y + xr[j].z * e0.z + xr[j].w * e0.w;
        }
#pragma unroll
        for (int off = 16; off; off >>= 1) a0 += __shfl_xor_sync(0xffffffffu, a0, off);
        float s0 = a0 - g_half_e2[i0];
        if (s0 > best || (s0 == best && i0 < bi)) { best = s0; bi = i0; }
    }

    if (lane == 0) {
        unsigned long long key =
            ((unsigned long long)ford(best) << 32) | (unsigned long long)(0xFFFFu - bi);
        atomicMax(&g_best[t], key);
    }
}

// ---------------- gather + masked write ---------------------------------------
__global__ __launch_bounds__(256)
void vq_gather(const int* __restrict__ ilen, const float* __restrict__ embed,
               float* __restrict__ outq, float* __restrict__ outi) {
    const int wid = threadIdx.x >> 5, lane = threadIdx.x & 31;
    const int t = blockIdx.x * 8 + wid;
    float4* oq = (float4*)outq;

    if ((t & (SS - 1)) >= ilen[t >> 11]) {
        float4 z = make_float4(0.f, 0.f, 0.f, 0.f);
#pragma unroll
        for (int j = 0; j < 4; j++) oq[(size_t)t * (DD / 4) + j * 32 + lane] = z;
        if (outi && lane == 0) outi[t] = -1.0f;
        return;
    }
    const int bi = 0xFFFF - (int)(g_best[t] & 0xFFFFFFFFull);
    const float4* e4 = (const float4*)embed;
#pragma unroll
    for (int j = 0; j < 4; j++)
        oq[(size_t)t * (DD / 4) + j * 32 + lane] = e4[(size_t)bi * (DD / 4) + j * 32 + lane];
    if (outi && lane == 0) outi[t] = (float)bi;
}

// ---------------- launch --------------------------------------------------------
extern "C" void kernel_launch(void* const* d_in, const int* in_sizes, int n_in,
                              void* d_out, int out_size) {
    const float* xp = nullptr;
    const int* lp = nullptr;
    const float* ep = nullptr;
    for (int i = 0; i < n_in; i++) {
        if (in_sizes[i] == MM * DD)      xp = (const float*)d_in[i];
        else if (in_sizes[i] == CC * DD) ep = (const float*)d_in[i];
        else if (in_sizes[i] == BB)      lp = (const int*)d_in[i];
    }
    float* oq = (float*)d_out;
    float* oi = (out_size >= (int)((size_t)MM * DD + MM)) ? oq + (size_t)MM * DD : nullptr;

    cudaFuncSetAttribute(vq_gemm, cudaFuncAttributeMaxDynamicSharedMemorySize, SMEM_DYN);

    prep_embed<<<CC / 8, 256>>>(ep);
    prep_x<<<MM / 8, 256>>>(xp);
    vq_gemm<<<dim3(256, SPLITS), 512, SMEM_DYN>>>(lp);
    vq_score<<<dim3(MM / 8, SPLITS), 256>>>(xp, lp, ep);
    vq_gather<<<MM / 8, 256>>>(lp, ep, oq, oi);
}